// round 1
// baseline (speedup 1.0000x reference)
#include <cuda_runtime.h>

#define NB 8
#define NN 2048
#define DF 128
#define NF 128

// Scratch (device globals — no allocation allowed)
__device__ float g_colsum[NB * NN];
__device__ float g_d[NB * NN];
__device__ float g_Xs[NB * NN * DF];
__device__ float g_Y[NB * NN * NF];

// ---------------------------------------------------------------------------
// 1. Zero the colsum accumulator (graph replays rerun everything, so must
//    re-zero every launch).
// ---------------------------------------------------------------------------
__global__ void k_zero() {
    int i = blockIdx.x * blockDim.x + threadIdx.x;
    if (i < NB * NN) g_colsum[i] = 0.0f;
}

// ---------------------------------------------------------------------------
// 2. Fused copy A -> out (first tuple element) + column sums of A.
//    d[b,j] = sum_i A_[b,i,j]  (axis=1 sum = column sums), +1 for I later.
//    Block: 256 threads = 256 consecutive columns; 128-row strip.
// ---------------------------------------------------------------------------
__global__ void k_copy_colsum(const float* __restrict__ A, float* __restrict__ outA) {
    int b  = blockIdx.z;
    int c  = blockIdx.x * 256 + threadIdx.x;
    int r0 = blockIdx.y * 128;
    const float* Ab = A    + (size_t)b * NN * NN;
    float*       Ob = outA + (size_t)b * NN * NN;
    float s = 0.0f;
    #pragma unroll 4
    for (int r = 0; r < 128; r++) {
        float v = Ab[(size_t)(r0 + r) * NN + c];
        Ob[(size_t)(r0 + r) * NN + c] = v;
        s += v;
    }
    atomicAdd(&g_colsum[b * NN + c], s);
}

// ---------------------------------------------------------------------------
// 3. d = rsqrt(colsum + 1)  and  Xs[b,j,f] = d[b,j] * X[b,j,f]
//    One block (128 threads = F dim) per (b,j) row.
// ---------------------------------------------------------------------------
__global__ void k_dscale(const float* __restrict__ X) {
    int row = blockIdx.x;                 // b*NN + j
    int f   = threadIdx.x;
    float dv = rsqrtf(g_colsum[row] + 1.0f);
    if (f == 0) g_d[row] = dv;
    g_Xs[(size_t)row * DF + f] = dv * X[(size_t)row * DF + f];
}

// ---------------------------------------------------------------------------
// 4. Main GEMM:  Y[b] = d .* (A[b] @ Xs[b] + Xs[b])   [2048x2048 @ 2048x128]
//    Block tile: 64 rows x 128 cols (full F), BK=32, 256 threads,
//    per-thread 8x4 register micro-tile. Warp layout: 32 lanes share a row
//    group (As reads broadcast), Bs read as float4 (conflict-free LDS.128).
// ---------------------------------------------------------------------------
#define BM 64
#define BK 32

__global__ __launch_bounds__(256) void k_gemm_AXs(const float* __restrict__ A) {
    int b  = blockIdx.y;
    int m0 = blockIdx.x * BM;

    __shared__ float As[BM][BK + 1];
    __shared__ float Bs[BK][NF + 4];

    const float* Ab = A    + (size_t)b * NN * NN;
    const float* Xb = g_Xs + (size_t)b * NN * DF;

    int tid = threadIdx.x;
    int tx  = tid & 31;   // col group: 4 cols each
    int ty  = tid >> 5;   // row group: 8 rows each (one warp per row group)

    float acc[8][4];
    #pragma unroll
    for (int r = 0; r < 8; r++)
        #pragma unroll
        for (int c = 0; c < 4; c++) acc[r][c] = 0.0f;

    for (int k0 = 0; k0 < NN; k0 += BK) {
        // Load As: 64x32 floats = 512 float4 loads, 2 per thread
        #pragma unroll
        for (int i = 0; i < 2; i++) {
            int idx = tid + i * 256;        // float4 index 0..511
            int r   = idx >> 3;             // /8 float4 per row
            int cc  = (idx & 7) << 2;
            float4 v = *(const float4*)&Ab[(size_t)(m0 + r) * NN + k0 + cc];
            As[r][cc + 0] = v.x; As[r][cc + 1] = v.y;
            As[r][cc + 2] = v.z; As[r][cc + 3] = v.w;
        }
        // Load Bs: 32x128 floats = 1024 float4 loads, 4 per thread
        #pragma unroll
        for (int i = 0; i < 4; i++) {
            int idx = tid + i * 256;        // 0..1023
            int r   = idx >> 5;             // /32 float4 per row
            int cc  = (idx & 31) << 2;
            float4 v = *(const float4*)&Xb[(size_t)(k0 + r) * DF + cc];
            *(float4*)&Bs[r][cc] = v;       // pad of 4 floats keeps 16B alignment
        }
        __syncthreads();

        #pragma unroll
        for (int kk = 0; kk < BK; kk++) {
            float a[8];
            #pragma unroll
            for (int r = 0; r < 8; r++) a[r] = As[ty * 8 + r][kk];   // broadcast in warp
            float4 bv = *(const float4*)&Bs[kk][tx * 4];             // LDS.128, conflict-free
            #pragma unroll
            for (int r = 0; r < 8; r++) {
                acc[r][0] += a[r] * bv.x;
                acc[r][1] += a[r] * bv.y;
                acc[r][2] += a[r] * bv.z;
                acc[r][3] += a[r] * bv.w;
            }
        }
        __syncthreads();
    }

    // Epilogue: Y[i,f] = d[i] * (acc + Xs[i,f])   (the +Xs term is the +I self-loop)
    float* Yb = g_Y + (size_t)b * NN * NF;
    #pragma unroll
    for (int r = 0; r < 8; r++) {
        int i = m0 + ty * 8 + r;
        float di = g_d[b * NN + i];
        #pragma unroll
        for (int c = 0; c < 4; c++) {
            int f = tx * 4 + c;
            Yb[(size_t)i * NF + f] = di * (acc[r][c] + Xb[(size_t)i * DF + f]);
        }
    }
}

// ---------------------------------------------------------------------------
// 5. H = relu(Y @ W)   [16384x128 @ 128x128] -> out H region.
//    Same tile structure; Y rows flattened across batches (W is shared).
// ---------------------------------------------------------------------------
__global__ __launch_bounds__(256) void k_gemm_YW(const float* __restrict__ W,
                                                 float* __restrict__ outH) {
    int m0 = blockIdx.x * BM;

    __shared__ float As[BM][BK + 1];
    __shared__ float Bs[BK][NF + 4];

    int tid = threadIdx.x;
    int tx  = tid & 31;
    int ty  = tid >> 5;

    float acc[8][4];
    #pragma unroll
    for (int r = 0; r < 8; r++)
        #pragma unroll
        for (int c = 0; c < 4; c++) acc[r][c] = 0.0f;

    for (int k0 = 0; k0 < DF; k0 += BK) {
        #pragma unroll
        for (int i = 0; i < 2; i++) {
            int idx = tid + i * 256;
            int r   = idx >> 3;
            int cc  = (idx & 7) << 2;
            float4 v = *(const float4*)&g_Y[(size_t)(m0 + r) * NF + k0 + cc];
            As[r][cc + 0] = v.x; As[r][cc + 1] = v.y;
            As[r][cc + 2] = v.z; As[r][cc + 3] = v.w;
        }
        #pragma unroll
        for (int i = 0; i < 4; i++) {
            int idx = tid + i * 256;
            int r   = idx >> 5;
            int cc  = (idx & 31) << 2;
            float4 v = *(const float4*)&W[(size_t)(k0 + r) * NF + cc];
            *(float4*)&Bs[r][cc] = v;
        }
        __syncthreads();

        #pragma unroll
        for (int kk = 0; kk < BK; kk++) {
            float a[8];
            #pragma unroll
            for (int r = 0; r < 8; r++) a[r] = As[ty * 8 + r][kk];
            float4 bv = *(const float4*)&Bs[kk][tx * 4];
            #pragma unroll
            for (int r = 0; r < 8; r++) {
                acc[r][0] += a[r] * bv.x;
                acc[r][1] += a[r] * bv.y;
                acc[r][2] += a[r] * bv.z;
                acc[r][3] += a[r] * bv.w;
            }
        }
        __syncthreads();
    }

    #pragma unroll
    for (int r = 0; r < 8; r++) {
        int i = m0 + ty * 8 + r;
        #pragma unroll
        for (int c = 0; c < 4; c++) {
            int f = tx * 4 + c;
            outH[(size_t)i * NF + f] = fmaxf(acc[r][c], 0.0f);
        }
    }
}

// ---------------------------------------------------------------------------
extern "C" void kernel_launch(void* const* d_in, const int* in_sizes, int n_in,
                              void* d_out, int out_size) {
    const float* A = (const float*)d_in[0];  // [8,2048,2048]
    const float* X = (const float*)d_in[1];  // [8,2048,128]
    const float* W = (const float*)d_in[2];  // [128,128]

    float* outA = (float*)d_out;                               // tuple elem 0
    float* outH = (float*)d_out + (size_t)NB * NN * NN;        // tuple elem 1

    k_zero<<<(NB * NN + 255) / 256, 256>>>();
    k_copy_colsum<<<dim3(NN / 256, NN / 128, NB), 256>>>(A, outA);
    k_dscale<<<NB * NN, DF>>>(X);
    k_gemm_AXs<<<dim3(NN / BM, NB), 256>>>(A);
    k_gemm_YW<<<dim3(NB * NN / BM), 256>>>(W, outH);
}

// round 6
// speedup vs baseline: 1.8502x; 1.8502x over previous
#include <cuda_runtime.h>
#include <cuda_fp16.h>
#include <cstdint>

#define NB 8
#define NN 2048
#define DF 128
#define NF 128

// ---------------- scratch (device globals; no allocation allowed) ----------
__device__ float  g_colsum[NB * NN];
__device__ float  g_d[NB * NN];
__device__ __half g_Xh[NB * NN * DF];   // split-hi of Xs = d*X, natural [b][j][f]
__device__ __half g_Xl[NB * NN * DF];   // split-lo
__device__ float  g_Y[NB * NN * NF];

// ---------------- helpers ---------------------------------------------------
__device__ __forceinline__ uint32_t smem_u32(const void* p) {
    uint32_t a;
    asm("{ .reg .u64 t; cvta.to.shared.u64 t, %1; cvt.u32.u64 %0, t; }"
        : "=r"(a) : "l"(p));
    return a;
}
__device__ __forceinline__ void ldmatrix_x4(uint32_t* r, uint32_t addr) {
    asm volatile("ldmatrix.sync.aligned.m8n8.x4.shared.b16 {%0,%1,%2,%3}, [%4];"
                 : "=r"(r[0]), "=r"(r[1]), "=r"(r[2]), "=r"(r[3]) : "r"(addr));
}
__device__ __forceinline__ void ldmatrix_x4_trans(uint32_t* r, uint32_t addr) {
    asm volatile("ldmatrix.sync.aligned.m8n8.x4.trans.shared.b16 {%0,%1,%2,%3}, [%4];"
                 : "=r"(r[0]), "=r"(r[1]), "=r"(r[2]), "=r"(r[3]) : "r"(addr));
}
__device__ __forceinline__ void mma16816(float* d, const uint32_t* a, const uint32_t* b) {
    asm volatile(
        "mma.sync.aligned.m16n8k16.row.col.f32.f16.f16.f32 "
        "{%0,%1,%2,%3}, {%4,%5,%6,%7}, {%8,%9}, {%0,%1,%2,%3};"
        : "+f"(d[0]), "+f"(d[1]), "+f"(d[2]), "+f"(d[3])
        : "r"(a[0]), "r"(a[1]), "r"(a[2]), "r"(a[3]), "r"(b[0]), "r"(b[1]));
}
__device__ __forceinline__ void split_f16(float v, uint16_t& hi, uint16_t& lo) {
    __half h = __float2half_rn(v);
    float hf = __half2float(h);
    __half l = __float2half_rn(v - hf);
    hi = __half_as_ushort(h);
    lo = __half_as_ushort(l);
}

// ---------------------------------------------------------------------------
// 1. zero colsum accumulator
// ---------------------------------------------------------------------------
__global__ void k_zero() {
    int i = blockIdx.x * blockDim.x + threadIdx.x;
    if (i < NB * NN) g_colsum[i] = 0.0f;
}

// ---------------------------------------------------------------------------
// 2. fused copy A->out + column sums (float4 vectorized)
// ---------------------------------------------------------------------------
__global__ __launch_bounds__(256) void k_copy_colsum(const float* __restrict__ A,
                                                     float* __restrict__ outA) {
    int b  = blockIdx.z;
    int c4 = blockIdx.x * 256 + threadIdx.x;
    int r0 = blockIdx.y * 128;
    const float4* Ab = (const float4*)(A    + (size_t)b * NN * NN) + c4;
    float4*       Ob = (float4*)      (outA + (size_t)b * NN * NN) + c4;
    float4 s = make_float4(0.f, 0.f, 0.f, 0.f);
    #pragma unroll 4
    for (int r = 0; r < 128; r++) {
        float4 v = Ab[(size_t)(r0 + r) * (NN / 4)];
        Ob[(size_t)(r0 + r) * (NN / 4)] = v;
        s.x += v.x; s.y += v.y; s.z += v.z; s.w += v.w;
    }
    float* cs = &g_colsum[b * NN + c4 * 4];
    atomicAdd(cs + 0, s.x);
    atomicAdd(cs + 1, s.y);
    atomicAdd(cs + 2, s.z);
    atomicAdd(cs + 3, s.w);
}

// ---------------------------------------------------------------------------
// 3. d = rsqrt(colsum+1); Xs = d*X split to fp16 hi/lo (natural layout).
//    One float4 (4 f-values) per thread.
// ---------------------------------------------------------------------------
__global__ __launch_bounds__(256) void k_dscale(const float* __restrict__ X) {
    int q   = blockIdx.x * 256 + threadIdx.x;         // float4 index
    int row = q >> 5;                                  // 32 float4 per row
    float dv = rsqrtf(g_colsum[row] + 1.0f);
    if ((q & 31) == 0) g_d[row] = dv;
    float4 v = ((const float4*)X)[q];
    uint16_t h0,l0,h1,l1,h2,l2,h3,l3;
    split_f16(dv * v.x, h0, l0); split_f16(dv * v.y, h1, l1);
    split_f16(dv * v.z, h2, l2); split_f16(dv * v.w, h3, l3);
    uint2 hv = make_uint2(((uint32_t)h1 << 16) | h0, ((uint32_t)h3 << 16) | h2);
    uint2 lv = make_uint2(((uint32_t)l1 << 16) | l0, ((uint32_t)l3 << 16) | l2);
    *(uint2*)&g_Xh[q * 4] = hv;
    *(uint2*)&g_Xl[q * 4] = lv;
}

// ---------------------------------------------------------------------------
// 4. HMMA GEMM: acc = Ah@Bh + Ah@Bl + Al@Bh  (fp32 acc, fp16 split operands)
//    CTA: 128x128 tile, K-tile 32, 8 warps (2x4), double-buffered smem.
//    Epilogue: Y[i,f] = d[i]*acc + d[i]*Xs[i,f]
// ---------------------------------------------------------------------------
#define KT 32
#define A_STR 40            // halves per A-tile row (pad 8 -> conflict-free ldmatrix)
#define B_STR 136           // halves per B-tile row (pad 8 -> conflict-free trans)
#define A_BYTES (128 * A_STR * 2)     // 10240
#define B_BYTES (KT * B_STR * 2)      // 8704
#define BUF_BYTES (2 * A_BYTES + 2 * B_BYTES)  // 37888
#define DYN_SMEM (2 * BUF_BYTES)               // 75776

__global__ __launch_bounds__(256, 1) void k_mma(const float* __restrict__ A,
                                                float* __restrict__ Y) {
    extern __shared__ char smem[];
    int tid  = threadIdx.x;
    int wid  = tid >> 5;
    int lane = tid & 31;
    int wm   = wid >> 2;        // 0..1 (64 rows each)
    int wn   = wid & 3;         // 0..3 (32 cols each)
    int b    = blockIdx.y;
    int m0   = blockIdx.x * 128;

    const float*  Ab  = A + (size_t)b * NN * NN + (size_t)m0 * NN;
    const __half* BhG = g_Xh + (size_t)b * NN * DF;
    const __half* BlG = g_Xl + (size_t)b * NN * DF;

    float acc[4][4][4];
    #pragma unroll
    for (int i = 0; i < 4; i++)
        #pragma unroll
        for (int j = 0; j < 4; j++)
            #pragma unroll
            for (int c = 0; c < 4; c++) acc[i][j][c] = 0.0f;

    // smem carve per buffer: [Ah | Al | Bh | Bl]
    auto ah_p = [&](int buf) { return smem + buf * BUF_BYTES; };
    auto al_p = [&](int buf) { return smem + buf * BUF_BYTES + A_BYTES; };
    auto bh_p = [&](int buf) { return smem + buf * BUF_BYTES + 2 * A_BYTES; };
    auto bl_p = [&](int buf) { return smem + buf * BUF_BYTES + 2 * A_BYTES + B_BYTES; };

    // per-thread load coordinates
    //   A: 4 float4 per thread; q = tid + i*256; row=q>>3 (8 quads/row), c4=q&7
    //   B: 2 uint4  per thread; q = tid + i*256; row=q>>4 (16 per row), u=q&15
    auto store_tile = [&](int buf, const float4* pa, const uint4* pbh, const uint4* pbl) {
        char* ah = ah_p(buf); char* al = al_p(buf);
        char* bh = bh_p(buf); char* bl = bl_p(buf);
        #pragma unroll
        for (int i = 0; i < 4; i++) {
            int q = tid + i * 256, row = q >> 3, c4 = q & 7;
            uint16_t h0,l0,h1,l1,h2,l2,h3,l3;
            split_f16(pa[i].x, h0, l0); split_f16(pa[i].y, h1, l1);
            split_f16(pa[i].z, h2, l2); split_f16(pa[i].w, h3, l3);
            uint2 hv = make_uint2(((uint32_t)h1 << 16) | h0, ((uint32_t)h3 << 16) | h2);
            uint2 lv = make_uint2(((uint32_t)l1 << 16) | l0, ((uint32_t)l3 << 16) | l2);
            int off = (row * A_STR + c4 * 4) * 2;
            *(uint2*)(ah + off) = hv;
            *(uint2*)(al + off) = lv;
        }
        #pragma unroll
        for (int i = 0; i < 2; i++) {
            int q = tid + i * 256, row = q >> 4, u = q & 15;
            int off = (row * B_STR + u * 8) * 2;
            *(uint4*)(bh + off) = pbh[i];
            *(uint4*)(bl + off) = pbl[i];
        }
    };
    auto load_tile_g = [&](int t, float4* pa, uint4* pbh, uint4* pbl) {
        int k0 = t * KT;
        #pragma unroll
        for (int i = 0; i < 4; i++) {
            int q = tid + i * 256, row = q >> 3, c4 = q & 7;
            pa[i] = *(const float4*)(Ab + (size_t)row * NN + k0 + c4 * 4);
        }
        #pragma unroll
        for (int i = 0; i < 2; i++) {
            int q = tid + i * 256, row = q >> 4, u = q & 15;
            pbh[i] = *(const uint4*)(BhG + (size_t)(k0 + row) * DF + u * 8);
            pbl[i] = *(const uint4*)(BlG + (size_t)(k0 + row) * DF + u * 8);
        }
    };

    {   // prologue: tile 0
        float4 pa[4]; uint4 pbh[2], pbl[2];
        load_tile_g(0, pa, pbh, pbl);
        store_tile(0, pa, pbh, pbl);
    }
    __syncthreads();

    const int NT = NN / KT;     // 64
    for (int t = 0; t < NT; t++) {
        int buf = t & 1;
        float4 pa[4]; uint4 pbh[2], pbl[2];
        if (t + 1 < NT) load_tile_g(t + 1, pa, pbh, pbl);

        // ---- compute on buf ----
        uint32_t aBase = smem_u32(ah_p(buf));
        uint32_t bBase = smem_u32(bh_p(buf));
        #pragma unroll
        for (int ks = 0; ks < KT; ks += 16) {
            uint32_t ah[4][4], al[4][4];
            #pragma unroll
            for (int mf = 0; mf < 4; mf++) {
                int row = wm * 64 + mf * 16 + (lane & 7) + ((lane >> 3) & 1) * 8;
                int col = ks + (lane >> 4) * 8;
                uint32_t ad = aBase + (row * A_STR + col) * 2;
                ldmatrix_x4(ah[mf], ad);
                ldmatrix_x4(al[mf], ad + A_BYTES);
            }
            uint32_t bh[4][2], bl[4][2];
            #pragma unroll
            for (int nh = 0; nh < 2; nh++) {
                int row = ks + ((lane >> 3) & 1) * 8 + (lane & 7);
                int col = wn * 32 + nh * 16 + (lane >> 4) * 8;
                uint32_t bd = bBase + (row * B_STR + col) * 2;
                uint32_t t4[4];
                ldmatrix_x4_trans(t4, bd);
                bh[2 * nh][0] = t4[0]; bh[2 * nh][1] = t4[1];
                bh[2 * nh + 1][0] = t4[2]; bh[2 * nh + 1][1] = t4[3];
                ldmatrix_x4_trans(t4, bd + B_BYTES);
                bl[2 * nh][0] = t4[0]; bl[2 * nh][1] = t4[1];
                bl[2 * nh + 1][0] = t4[2]; bl[2 * nh + 1][1] = t4[3];
            }
            #pragma unroll
            for (int mf = 0; mf < 4; mf++)
                #pragma unroll
                for (int nf = 0; nf < 4; nf++) {
                    mma16816(acc[mf][nf], ah[mf], bh[nf]);
                    mma16816(acc[mf][nf], ah[mf], bl[nf]);
                    mma16816(acc[mf][nf], al[mf], bh[nf]);
                }
        }

        if (t + 1 < NT) store_tile(buf ^ 1, pa, pbh, pbl);
        __syncthreads();
    }

    // ---- epilogue: Y[i,f] = d[i]*acc + d[i]*Xs_hi_approx... use d*acc + d*Xs
    //      exact: Y = d_i * (A@Xs)_i + d_i * Xs_i ; Xs = d*X recomputed from X? use d^2*X
    //      Here: reconstruct with d_i * acc + d_i*d_i*X — but X not passed; use
    //      Xs = (g_Xh + g_Xl) in fp32, which equals d*X to ~2^-22.
    float* Yb = Y + (size_t)b * NN * NF;
    #pragma unroll
    for (int mf = 0; mf < 4; mf++) {
        int row = m0 + wm * 64 + mf * 16 + (lane >> 2);
        float d0 = g_d[b * NN + row];
        float d1 = g_d[b * NN + row + 8];
        #pragma unroll
        for (int nf = 0; nf < 4; nf++) {
            int col = wn * 32 + nf * 8 + (lane & 3) * 2;
            const __half* xh0 = BhG + (size_t)(row - m0 + m0) * DF + col;
            // self-loop term: Xs[i,f] = hi+lo
            float xs00 = __half2float(g_Xh[((size_t)b * NN + row) * DF + col])
                       + __half2float(g_Xl[((size_t)b * NN + row) * DF + col]);
            float xs01 = __half2float(g_Xh[((size_t)b * NN + row) * DF + col + 1])
                       + __half2float(g_Xl[((size_t)b * NN + row) * DF + col + 1]);
            float xs10 = __half2float(g_Xh[((size_t)b * NN + row + 8) * DF + col])
                       + __half2float(g_Xl[((size_t)b * NN + row + 8) * DF + col]);
            float xs11 = __half2float(g_Xh[((size_t)b * NN + row + 8) * DF + col + 1])
                       + __half2float(g_Xl[((size_t)b * NN + row + 8) * DF + col + 1]);
            float2 o0 = make_float2(d0 * (acc[mf][nf][0] + xs00),
                                    d0 * (acc[mf][nf][1] + xs01));
            float2 o1 = make_float2(d1 * (acc[mf][nf][2] + xs10),
                                    d1 * (acc[mf][nf][3] + xs11));
            *(float2*)&Yb[(size_t)row * NF + col] = o0;
            *(float2*)&Yb[(size_t)(row + 8) * NF + col] = o1;
            (void)xh0;
        }
    }
}

// ---------------------------------------------------------------------------
// 5. H = relu(Y @ W)  [16384x128 @ 128x128] (fp32 SIMT)
// ---------------------------------------------------------------------------
#define BM 64
#define BK 32
__global__ __launch_bounds__(256) void k_gemm_YW(const float* __restrict__ W,
                                                 float* __restrict__ outH) {
    int m0 = blockIdx.x * BM;
    __shared__ float As[BM][BK + 1];
    __shared__ float Bs[BK][NF + 4];
    int tid = threadIdx.x;
    int tx  = tid & 31;
    int ty  = tid >> 5;

    float acc[8][4];
    #pragma unroll
    for (int r = 0; r < 8; r++)
        #pragma unroll
        for (int c = 0; c < 4; c++) acc[r][c] = 0.0f;

    for (int k0 = 0; k0 < DF; k0 += BK) {
        #pragma unroll
        for (int i = 0; i < 2; i++) {
            int idx = tid + i * 256;
            int r = idx >> 3;
            int cc = (idx & 7) << 2;
            float4 v = *(const float4*)&g_Y[(size_t)(m0 + r) * NF + k0 + cc];
            As[r][cc+0] = v.x; As[r][cc+1] = v.y; As[r][cc+2] = v.z; As[r][cc+3] = v.w;
        }
        #pragma unroll
        for (int i = 0; i < 4; i++) {
            int idx = tid + i * 256;
            int r = idx >> 5;
            int cc = (idx & 31) << 2;
            float4 v = *(const float4*)&W[(size_t)(k0 + r) * NF + cc];
            *(float4*)&Bs[r][cc] = v;
        }
        __syncthreads();
        #pragma unroll
        for (int kk = 0; kk < BK; kk++) {
            float a[8];
            #pragma unroll
            for (int r = 0; r < 8; r++) a[r] = As[ty * 8 + r][kk];
            float4 bv = *(const float4*)&Bs[kk][tx * 4];
            #pragma unroll
            for (int r = 0; r < 8; r++) {
                acc[r][0] += a[r] * bv.x;
                acc[r][1] += a[r] * bv.y;
                acc[r][2] += a[r] * bv.z;
                acc[r][3] += a[r] * bv.w;
            }
        }
        __syncthreads();
    }
    #pragma unroll
    for (int r = 0; r < 8; r++) {
        int i = m0 + ty * 8 + r;
        #pragma unroll
        for (int c = 0; c < 4; c++)
            outH[(size_t)i * NF + tx * 4 + c] = fmaxf(acc[r][c], 0.0f);
    }
}

// ---------------------------------------------------------------------------
extern "C" void kernel_launch(void* const* d_in, const int* in_sizes, int n_in,
                              void* d_out, int out_size) {
    const float* A = (const float*)d_in[0];
    const float* X = (const float*)d_in[1];
    const float* W = (const float*)d_in[2];

    float* outA = (float*)d_out;
    float* outH = (float*)d_out + (size_t)NB * NN * NN;

    static bool attr_set = false;
    if (!attr_set) {
        cudaFuncSetAttribute(k_mma, cudaFuncAttributeMaxDynamicSharedMemorySize, DYN_SMEM);
        attr_set = true;
    }

    float* Y;
    cudaGetSymbolAddress((void**)&Y, g_Y);

    k_zero<<<(NB * NN + 255) / 256, 256>>>();
    k_copy_colsum<<<dim3(NN / 4 / 256, NN / 128, NB), 256>>>(A, outA);
    k_dscale<<<(NB * NN * DF / 4) / 256, 256>>>(X);
    k_mma<<<dim3(NN / 128, NB), 256, DYN_SMEM>>>(A, Y);
    k_gemm_YW<<<dim3(NB * NN / BM), 256>>>(W, outH);
}